// round 8
// baseline (speedup 1.0000x reference)
#include <cuda_runtime.h>
#include <cstdint>

typedef unsigned u32;

#define NPX (512 * 1024)
#define LRN (256 * 512)
#define NTILES 4096            // 4096 tiles x 128 px
#define BSTR 136               // act buffer row stride (floats)

// ---------------- tf32 weights (padded layouts) in global scratch ----------------
__device__ __align__(16) u32 g_wt0[128 * 132];
__device__ __align__(16) u32 g_wt1[64 * 132];
__device__ __align__(16) u32 g_wt2[32 * 68];
__device__ __align__(16) u32 g_wt3[16 * 36];

__device__ __forceinline__ u32 f2tf(float f) {
    u32 r; asm("cvt.rna.tf32.f32 %0, %1;" : "=r"(r) : "f"(f)); return r;
}
__device__ __forceinline__ float lrelu(float x) { return fmaxf(x, 0.01f * x); }

// ---------------- prep: fp32 -> tf32 padded weight layouts ----------------
__global__ void cmfsm_prep(const float* __restrict__ w0, const float* __restrict__ w1,
                           const float* __restrict__ w2, const float* __restrict__ w3) {
    int t = blockIdx.x * blockDim.x + threadIdx.x;
    int n = gridDim.x * blockDim.x;
    for (int i = t; i < 128 * 128; i += n) { int j = i >> 7, k = i & 127; g_wt0[j * 132 + k] = f2tf(w0[i]); }
    for (int i = t; i < 64 * 128;  i += n) { int j = i >> 7, k = i & 127; g_wt1[j * 132 + k] = f2tf(w1[i]); }
    for (int i = t; i < 32 * 64;   i += n) { int j = i >> 6, k = i & 63;  g_wt2[j * 68  + k] = f2tf(w2[i]); }
    for (int i = t; i < 16 * 32;   i += n) { int j = i >> 5, k = i & 31;  g_wt3[j * 36  + k] = f2tf(w3[i]); }
}

// ---------------- smem layout (bytes) ----------------
#define OBUF  0                         // act buffer: 128 rows x 136 f32 = 69632
#define OSW0  69632                     // 128x132 u32 = 67584
#define OSW1  137216                    // 64x132 = 33792
#define OSW2  171008                    // 32x68  = 8704
#define OSW3  179712                    // 16x36  = 2304
#define OSACT 182016                    // 128 px x 17 f32 = 8704
#define SMEMSZ 190720

// ---------------- mma.m16n8k8 tf32 ----------------
__device__ __forceinline__ void mma8(float* c, const u32* a, u32 b0, u32 b1) {
    asm volatile(
        "mma.sync.aligned.m16n8k8.row.col.f32.tf32.tf32.f32 "
        "{%0,%1,%2,%3}, {%4,%5,%6,%7}, {%8,%9}, {%0,%1,%2,%3};"
        : "+f"(c[0]), "+f"(c[1]), "+f"(c[2]), "+f"(c[3])
        : "r"(a[0]), "r"(a[1]), "r"(a[2]), "r"(a[3]), "r"(b0), "r"(b1));
}

// A-fragment: W[m0+r][k0+c], +8 rows, +4 cols  (r=lane>>2, c=lane&3)
__device__ __forceinline__ void lda(const u32* W, int S, int m0, int k0, int lane, u32* a) {
    int r = lane >> 2, c = lane & 3;
    const u32* p = W + (m0 + r) * S + k0 + c;
    a[0] = p[0];
    a[2] = p[4];
    a[1] = p[8 * S];
    a[3] = p[8 * S + 4];
}

// GEMM: C[MT][NT][4] += Wtf32 @ split(act).  K = 8*KT.
template <int MT, int NT, int KT, int WS>
__device__ __forceinline__ void gemm(const u32* W, const float* buf, float* C,
                                     int m0, int px0, int lane) {
    const int r = lane >> 2, c = lane & 3;
#pragma unroll 1
    for (int kt = 0; kt < KT; kt++) {
        const int k0 = kt * 8;
        u32 a[MT][4];
#pragma unroll
        for (int mt = 0; mt < MT; mt++) lda(W, WS, m0 + 16 * mt, k0, lane, a[mt]);
#pragma unroll
        for (int nt = 0; nt < NT; nt++) {
            float y0 = buf[(k0 + c) * BSTR + px0 + 8 * nt + r];
            float y1 = buf[(k0 + 4 + c) * BSTR + px0 + 8 * nt + r];
            u32 h0 = f2tf(y0), h1 = f2tf(y1);
            u32 l0 = f2tf(y0 - __uint_as_float(h0));
            u32 l1 = f2tf(y1 - __uint_as_float(h1));
#pragma unroll
            for (int mt = 0; mt < MT; mt++) {
                mma8(C + (mt * NT + nt) * 4, a[mt], h0, h1);
                mma8(C + (mt * NT + nt) * 4, a[mt], l0, l1);
            }
        }
    }
}

// epilogue: lrelu(C) -> buf (fp32), in place over inputs (caller syncs first)
template <int MT, int NT>
__device__ __forceinline__ void epi(float* buf, const float* C, int m0, int px0, int lane) {
    const int r = lane >> 2, c = lane & 3;
#pragma unroll
    for (int mt = 0; mt < MT; mt++)
#pragma unroll
        for (int nt = 0; nt < NT; nt++) {
            const float* cc = C + (mt * NT + nt) * 4;
            int ch = m0 + 16 * mt + r;
            int px = px0 + 8 * nt + 2 * c;
            float2 v0 = { lrelu(cc[0]), lrelu(cc[1]) };
            float2 v1 = { lrelu(cc[2]), lrelu(cc[3]) };
            *(float2*)(buf + ch * BSTR + px)       = v0;
            *(float2*)(buf + (ch + 8) * BSTR + px) = v1;
        }
}

__global__ void __launch_bounds__(512, 1)
cmfsm_main(const float* __restrict__ lr, const float* __restrict__ hr,
           const float* __restrict__ w4, const float* __restrict__ w5,
           const float* __restrict__ s2w0, const float* __restrict__ s2w1,
           const float* __restrict__ s2w2, const float* __restrict__ fw,
           float* __restrict__ out) {
    extern __shared__ __align__(16) char sm8[];
    float* buf  = (float*)(sm8 + OBUF);
    u32*  sw0   = (u32*)(sm8 + OSW0);
    u32*  sw1   = (u32*)(sm8 + OSW1);
    u32*  sw2   = (u32*)(sm8 + OSW2);
    u32*  sw3   = (u32*)(sm8 + OSW3);
    float* sact = (float*)(sm8 + OSACT);

    const int tid  = threadIdx.x;
    const int wid  = tid >> 5;
    const int lane = tid & 31;

    // weights: L2 scratch -> smem, once per (persistent) block
    {
        const uint4* s0 = (const uint4*)g_wt0; uint4* d0 = (uint4*)sw0;
        for (int i = tid; i < 4224; i += 512) d0[i] = s0[i];
        const uint4* s1 = (const uint4*)g_wt1; uint4* d1 = (uint4*)sw1;
        for (int i = tid; i < 2112; i += 512) d1[i] = s1[i];
        const uint4* s2 = (const uint4*)g_wt2; uint4* d2 = (uint4*)sw2;
        for (int i = tid; i < 544; i += 512) d2[i] = s2[i];
        const uint4* s3 = (const uint4*)g_wt3; uint4* d3 = (uint4*)sw3;
        for (int i = tid; i < 144; i += 512) d3[i] = s3[i];
    }
    __syncthreads();

    for (int tile = blockIdx.x; tile < NTILES; tile += gridDim.x) {
        const int pxb = tile << 7;
        const int hb  = pxb >> 10;
        const int wbp = pxb & 1023;

        // ---- rep build: rows 0-31 a, 32-63 b, 64-95 a*b, 96-127 (a-b)^2 ----
        {
            const int g  = tid >> 7;          // 0..3 -> 8 channels each
            const int px = tid & 127;
            const int li = ((hb >> 1) << 9) + ((wbp + px) >> 1);
            const float* hp = hr + (size_t)(8 * g) * NPX + (pxb + px);
            const float* lp = lr + (size_t)(8 * g) * LRN + li;
#pragma unroll
            for (int i = 0; i < 8; i++) {
                float a = lp[(size_t)i * LRN];
                float b = hp[(size_t)i * NPX];
                int cch = 8 * g + i;
                buf[cch * BSTR + px]        = a;
                buf[(32 + cch) * BSTR + px] = b;
                buf[(64 + cch) * BSTR + px] = a * b;
                float d = a - b;
                buf[(96 + cch) * BSTR + px] = d * d;
            }
        }
        __syncthreads();

        // ---- GEMM1: 128 <- rep(128); warp grid 4(m) x 4(px) ----
        {
            float C1[2 * 4 * 4];
#pragma unroll
            for (int i = 0; i < 32; i++) C1[i] = 0.f;
            int m0 = 32 * (wid & 3), px0 = 32 * (wid >> 2);
            gemm<2, 4, 16, 132>(sw0, buf, C1, m0, px0, lane);
            __syncthreads();
            epi<2, 4>(buf, C1, m0, px0, lane);
        }
        __syncthreads();

        // ---- GEMM2: 64 <- act1(128); warp grid 2(m) x 8(px) ----
        {
            float C2[2 * 2 * 4];
#pragma unroll
            for (int i = 0; i < 16; i++) C2[i] = 0.f;
            int m0 = 32 * (wid & 1), px0 = 16 * (wid >> 1);
            gemm<2, 2, 16, 132>(sw1, buf, C2, m0, px0, lane);
            __syncthreads();
            epi<2, 2>(buf, C2, m0, px0, lane);
        }
        __syncthreads();

        // ---- GEMM3: 32 <- act2(64); warp grid 2(m) x 8(px) ----
        {
            float C3[1 * 2 * 4];
#pragma unroll
            for (int i = 0; i < 8; i++) C3[i] = 0.f;
            int m0 = 16 * (wid & 1), px0 = 16 * (wid >> 1);
            gemm<1, 2, 8, 68>(sw2, buf, C3, m0, px0, lane);
            __syncthreads();
            epi<1, 2>(buf, C3, m0, px0, lane);
        }
        __syncthreads();

        // ---- GEMM4: 16 <- act3(32); 16 warps x 8 px -> SACT [px][16] ----
        {
            float C4[4];
#pragma unroll
            for (int i = 0; i < 4; i++) C4[i] = 0.f;
            int px0 = 8 * wid;
            gemm<1, 1, 4, 36>(sw3, buf, C4, 0, px0, lane);
            const int r = lane >> 2, c = lane & 3;
            int px = px0 + 2 * c;
            sact[px * 17 + r]           = lrelu(C4[0]);
            sact[(px + 1) * 17 + r]     = lrelu(C4[1]);
            sact[px * 17 + r + 8]       = lrelu(C4[2]);
            sact[(px + 1) * 17 + r + 8] = lrelu(C4[3]);
        }
        __syncthreads();

        // ---- scalar finish: layers 5,6 + weights2 + fuse ----
        if (tid < 128) {
            const float* o4 = sact + tid * 17;
            float w1v = 0.f;
#pragma unroll
            for (int cc = 0; cc < 8; cc++) {
                float n5 = 0.f;
#pragma unroll
                for (int k = 0; k < 16; k++) n5 = fmaf(w4[cc * 16 + k], o4[k], n5);
                w1v = fmaf(w5[cc], n5, w1v);
            }
            float dx = ((wbp + tid) & 1) ? 1.0f : -1.0f;
            float dy = (hb & 1) ? 1.0f : -1.0f;
            const float nm = 1.41421356237309515f;
            float t0 = lrelu(s2w0[0] * dx + s2w0[1] * dy + s2w0[2] * nm);
            float t1 = lrelu(s2w0[3] * dx + s2w0[4] * dy + s2w0[5] * nm);
            float t2 = lrelu(s2w0[6] * dx + s2w0[7] * dy + s2w0[8] * nm);
            float u0 = lrelu(s2w1[0] * t0 + s2w1[1] * t1 + s2w1[2] * t2);
            float u1 = lrelu(s2w1[3] * t0 + s2w1[4] * t1 + s2w1[5] * t2);
            float w2v = s2w2[0] * u0 + s2w2[1] * u1;
            out[pxb + tid] = fabsf(fw[0]) * w1v + fabsf(fw[1]) * w2v;
        }
        __syncthreads();
    }
}

extern "C" void kernel_launch(void* const* d_in, const int* in_sizes, int n_in,
                              void* d_out, int out_size) {
    const float* lr   = (const float*)d_in[0];
    const float* hr   = (const float*)d_in[1];
    const float* w0   = (const float*)d_in[2];
    const float* w1   = (const float*)d_in[3];
    const float* w2   = (const float*)d_in[4];
    const float* w3   = (const float*)d_in[5];
    const float* w4   = (const float*)d_in[6];
    const float* w5   = (const float*)d_in[7];
    const float* s2w0 = (const float*)d_in[8];
    const float* s2w1 = (const float*)d_in[9];
    const float* s2w2 = (const float*)d_in[10];
    const float* fw   = (const float*)d_in[11];

    cmfsm_prep<<<64, 256>>>(w0, w1, w2, w3);

    int sms = 148;
    cudaDeviceGetAttribute(&sms, cudaDevAttrMultiProcessorCount, 0);
    if (sms > NTILES) sms = NTILES;

    cudaFuncSetAttribute(cmfsm_main, cudaFuncAttributeMaxDynamicSharedMemorySize, SMEMSZ);
    cmfsm_main<<<sms, 512, SMEMSZ>>>(lr, hr, w4, w5, s2w0, s2w1, s2w2, fw, (float*)d_out);
}

// round 9
// speedup vs baseline: 1.5898x; 1.5898x over previous
#include <cuda_runtime.h>
#include <cstdint>

typedef unsigned u32;

#define NPX (512 * 1024)
#define LRN (256 * 512)
#define NTILES 4096            // 4096 tiles x 128 px
#define BSTR 136               // act buffer row stride (floats)

// ---------------- tf32 weights (padded layouts) in global scratch ----------------
__device__ __align__(16) u32 g_wt0[128 * 132];
__device__ __align__(16) u32 g_wt1[64 * 132];
__device__ __align__(16) u32 g_wt2[32 * 68];
__device__ __align__(16) u32 g_wt3[16 * 36];

__device__ __forceinline__ u32 f2tf(float f) {
    u32 r; asm("cvt.rna.tf32.f32 %0, %1;" : "=r"(r) : "f"(f)); return r;
}
__device__ __forceinline__ float lrelu(float x) { return fmaxf(x, 0.01f * x); }

// ---------------- prep: fp32 -> tf32 padded weight layouts ----------------
__global__ void cmfsm_prep(const float* __restrict__ w0, const float* __restrict__ w1,
                           const float* __restrict__ w2, const float* __restrict__ w3) {
    int t = blockIdx.x * blockDim.x + threadIdx.x;
    int n = gridDim.x * blockDim.x;
    for (int i = t; i < 128 * 128; i += n) { int j = i >> 7, k = i & 127; g_wt0[j * 132 + k] = f2tf(w0[i]); }
    for (int i = t; i < 64 * 128;  i += n) { int j = i >> 7, k = i & 127; g_wt1[j * 132 + k] = f2tf(w1[i]); }
    for (int i = t; i < 32 * 64;   i += n) { int j = i >> 6, k = i & 63;  g_wt2[j * 68  + k] = f2tf(w2[i]); }
    for (int i = t; i < 16 * 32;   i += n) { int j = i >> 5, k = i & 31;  g_wt3[j * 36  + k] = f2tf(w3[i]); }
}

// ---------------- smem layout (bytes) ----------------
#define OBUF  0                         // act buffer: 128 rows x 136 f32 = 69632
#define OSW0  69632                     // 128x132 u32 = 67584
#define OSW1  137216                    // 64x132 = 33792
#define OSW2  171008                    // 32x68  = 8704
#define OSW3  179712                    // 16x36  = 2304
#define OSACT 182016                    // 128 px x 17 f32 = 8704
#define SMEMSZ 190720

// ---------------- mma.m16n8k8 tf32 ----------------
__device__ __forceinline__ void mma8(float* c, const u32* a, u32 b0, u32 b1) {
    asm volatile(
        "mma.sync.aligned.m16n8k8.row.col.f32.tf32.tf32.f32 "
        "{%0,%1,%2,%3}, {%4,%5,%6,%7}, {%8,%9}, {%0,%1,%2,%3};"
        : "+f"(c[0]), "+f"(c[1]), "+f"(c[2]), "+f"(c[3])
        : "r"(a[0]), "r"(a[1]), "r"(a[2]), "r"(a[3]), "r"(b0), "r"(b1));
}

// A-fragment: W[m0+r][k0+c], +8 rows, +4 cols  (r=lane>>2, c=lane&3)
__device__ __forceinline__ void lda(const u32* W, int S, int m0, int k0, int lane, u32* a) {
    int r = lane >> 2, c = lane & 3;
    const u32* p = W + (m0 + r) * S + k0 + c;
    a[0] = p[0];
    a[2] = p[4];
    a[1] = p[8 * S];
    a[3] = p[8 * S + 4];
}

// GEMM: C[MT][NT][4] += Wtf32 @ split(act).  K = 8*KT.
// kt unrolled x2: next iteration's LDS/cvt overlap current iteration's MMAs.
template <int MT, int NT, int KT, int WS>
__device__ __forceinline__ void gemm(const u32* W, const float* buf, float* C,
                                     int m0, int px0, int lane) {
    const int r = lane >> 2, c = lane & 3;
#pragma unroll 2
    for (int kt = 0; kt < KT; kt++) {
        const int k0 = kt * 8;
        u32 a[MT][4];
#pragma unroll
        for (int mt = 0; mt < MT; mt++) lda(W, WS, m0 + 16 * mt, k0, lane, a[mt]);
#pragma unroll
        for (int nt = 0; nt < NT; nt++) {
            float y0 = buf[(k0 + c) * BSTR + px0 + 8 * nt + r];
            float y1 = buf[(k0 + 4 + c) * BSTR + px0 + 8 * nt + r];
            u32 h0 = f2tf(y0), h1 = f2tf(y1);
            u32 l0 = f2tf(y0 - __uint_as_float(h0));
            u32 l1 = f2tf(y1 - __uint_as_float(h1));
#pragma unroll
            for (int mt = 0; mt < MT; mt++) {
                mma8(C + (mt * NT + nt) * 4, a[mt], h0, h1);
                mma8(C + (mt * NT + nt) * 4, a[mt], l0, l1);
            }
        }
    }
}

// epilogue: lrelu(C) -> buf (fp32), in place over inputs (caller syncs first)
template <int MT, int NT>
__device__ __forceinline__ void epi(float* buf, const float* C, int m0, int px0, int lane) {
    const int r = lane >> 2, c = lane & 3;
#pragma unroll
    for (int mt = 0; mt < MT; mt++)
#pragma unroll
        for (int nt = 0; nt < NT; nt++) {
            const float* cc = C + (mt * NT + nt) * 4;
            int ch = m0 + 16 * mt + r;
            int px = px0 + 8 * nt + 2 * c;
            float2 v0 = { lrelu(cc[0]), lrelu(cc[1]) };
            float2 v1 = { lrelu(cc[2]), lrelu(cc[3]) };
            *(float2*)(buf + ch * BSTR + px)       = v0;
            *(float2*)(buf + (ch + 8) * BSTR + px) = v1;
        }
}

__global__ void __launch_bounds__(256, 1)
cmfsm_main(const float* __restrict__ lr, const float* __restrict__ hr,
           const float* __restrict__ w4, const float* __restrict__ w5,
           const float* __restrict__ s2w0, const float* __restrict__ s2w1,
           const float* __restrict__ s2w2, const float* __restrict__ fw,
           float* __restrict__ out) {
    extern __shared__ __align__(16) char sm8[];
    float* buf  = (float*)(sm8 + OBUF);
    u32*  sw0   = (u32*)(sm8 + OSW0);
    u32*  sw1   = (u32*)(sm8 + OSW1);
    u32*  sw2   = (u32*)(sm8 + OSW2);
    u32*  sw3   = (u32*)(sm8 + OSW3);
    float* sact = (float*)(sm8 + OSACT);

    const int tid  = threadIdx.x;
    const int wid  = tid >> 5;
    const int lane = tid & 31;

    // weights: L2 scratch -> smem, once per (persistent) block
    {
        const uint4* s0 = (const uint4*)g_wt0; uint4* d0 = (uint4*)sw0;
        for (int i = tid; i < 4224; i += 256) d0[i] = s0[i];
        const uint4* s1 = (const uint4*)g_wt1; uint4* d1 = (uint4*)sw1;
        for (int i = tid; i < 2112; i += 256) d1[i] = s1[i];
        const uint4* s2 = (const uint4*)g_wt2; uint4* d2 = (uint4*)sw2;
        for (int i = tid; i < 544; i += 256) d2[i] = s2[i];
        const uint4* s3 = (const uint4*)g_wt3; uint4* d3 = (uint4*)sw3;
        for (int i = tid; i < 144; i += 256) d3[i] = s3[i];
    }
    __syncthreads();

    for (int tile = blockIdx.x; tile < NTILES; tile += gridDim.x) {
        const int pxb = tile << 7;
        const int hb  = pxb >> 10;
        const int wbp = pxb & 1023;

        // ---- rep build: rows 0-31 a, 32-63 b, 64-95 a*b, 96-127 (a-b)^2 ----
        {
            const int g  = tid >> 7;          // 0..1 -> 16 channels each
            const int px = tid & 127;
            const int li = ((hb >> 1) << 9) + ((wbp + px) >> 1);
            const float* hp = hr + (size_t)(16 * g) * NPX + (pxb + px);
            const float* lp = lr + (size_t)(16 * g) * LRN + li;
#pragma unroll
            for (int i = 0; i < 16; i++) {
                float a = lp[(size_t)i * LRN];
                float b = hp[(size_t)i * NPX];
                int cch = 16 * g + i;
                buf[cch * BSTR + px]        = a;
                buf[(32 + cch) * BSTR + px] = b;
                buf[(64 + cch) * BSTR + px] = a * b;
                float d = a - b;
                buf[(96 + cch) * BSTR + px] = d * d;
            }
        }
        __syncthreads();

        // ---- GEMM1: 128 <- rep(128); warp grid 4(m) x 2(px) ----
        {
            float C1[2 * 8 * 4];
#pragma unroll
            for (int i = 0; i < 64; i++) C1[i] = 0.f;
            int m0 = 32 * (wid & 3), px0 = 64 * (wid >> 2);
            gemm<2, 8, 16, 132>(sw0, buf, C1, m0, px0, lane);
            __syncthreads();
            epi<2, 8>(buf, C1, m0, px0, lane);
        }
        __syncthreads();

        // ---- GEMM2: 64 <- act1(128); warp grid 2(m) x 4(px) ----
        {
            float C2[2 * 4 * 4];
#pragma unroll
            for (int i = 0; i < 32; i++) C2[i] = 0.f;
            int m0 = 32 * (wid & 1), px0 = 32 * (wid >> 1);
            gemm<2, 4, 16, 132>(sw1, buf, C2, m0, px0, lane);
            __syncthreads();
            epi<2, 4>(buf, C2, m0, px0, lane);
        }
        __syncthreads();

        // ---- GEMM3: 32 <- act2(64); warp grid 2(m) x 4(px) ----
        {
            float C3[1 * 4 * 4];
#pragma unroll
            for (int i = 0; i < 16; i++) C3[i] = 0.f;
            int m0 = 16 * (wid & 1), px0 = 32 * (wid >> 1);
            gemm<1, 4, 8, 68>(sw2, buf, C3, m0, px0, lane);
            __syncthreads();
            epi<1, 4>(buf, C3, m0, px0, lane);
        }
        __syncthreads();

        // ---- GEMM4: 16 <- act3(32); 8 warps x 16 px (NT=2) -> SACT [px][16] ----
        {
            float C4[2 * 4];
#pragma unroll
            for (int i = 0; i < 8; i++) C4[i] = 0.f;
            int px0 = 16 * wid;
            gemm<1, 2, 4, 36>(sw3, buf, C4, 0, px0, lane);
            const int r = lane >> 2, c = lane & 3;
#pragma unroll
            for (int nt = 0; nt < 2; nt++) {
                const float* cc = C4 + nt * 4;
                int px = px0 + 8 * nt + 2 * c;
                sact[px * 17 + r]           = lrelu(cc[0]);
                sact[(px + 1) * 17 + r]     = lrelu(cc[1]);
                sact[px * 17 + r + 8]       = lrelu(cc[2]);
                sact[(px + 1) * 17 + r + 8] = lrelu(cc[3]);
            }
        }
        __syncthreads();

        // ---- scalar finish: layers 5,6 + weights2 + fuse ----
        if (tid < 128) {
            const float* o4 = sact + tid * 17;
            float w1v = 0.f;
#pragma unroll
            for (int cc = 0; cc < 8; cc++) {
                float n5 = 0.f;
#pragma unroll
                for (int k = 0; k < 16; k++) n5 = fmaf(w4[cc * 16 + k], o4[k], n5);
                w1v = fmaf(w5[cc], n5, w1v);
            }
            float dx = ((wbp + tid) & 1) ? 1.0f : -1.0f;
            float dy = (hb & 1) ? 1.0f : -1.0f;
            const float nm = 1.41421356237309515f;
            float t0 = lrelu(s2w0[0] * dx + s2w0[1] * dy + s2w0[2] * nm);
            float t1 = lrelu(s2w0[3] * dx + s2w0[4] * dy + s2w0[5] * nm);
            float t2 = lrelu(s2w0[6] * dx + s2w0[7] * dy + s2w0[8] * nm);
            float u0 = lrelu(s2w1[0] * t0 + s2w1[1] * t1 + s2w1[2] * t2);
            float u1 = lrelu(s2w1[3] * t0 + s2w1[4] * t1 + s2w1[5] * t2);
            float w2v = s2w2[0] * u0 + s2w2[1] * u1;
            out[pxb + tid] = fabsf(fw[0]) * w1v + fabsf(fw[1]) * w2v;
        }
        __syncthreads();
    }
}

extern "C" void kernel_launch(void* const* d_in, const int* in_sizes, int n_in,
                              void* d_out, int out_size) {
    const float* lr   = (const float*)d_in[0];
    const float* hr   = (const float*)d_in[1];
    const float* w0   = (const float*)d_in[2];
    const float* w1   = (const float*)d_in[3];
    const float* w2   = (const float*)d_in[4];
    const float* w3   = (const float*)d_in[5];
    const float* w4   = (const float*)d_in[6];
    const float* w5   = (const float*)d_in[7];
    const float* s2w0 = (const float*)d_in[8];
    const float* s2w1 = (const float*)d_in[9];
    const float* s2w2 = (const float*)d_in[10];
    const float* fw   = (const float*)d_in[11];

    cmfsm_prep<<<64, 256>>>(w0, w1, w2, w3);

    int sms = 148;
    cudaDeviceGetAttribute(&sms, cudaDevAttrMultiProcessorCount, 0);
    if (sms > NTILES) sms = NTILES;

    cudaFuncSetAttribute(cmfsm_main, cudaFuncAttributeMaxDynamicSharedMemorySize, SMEMSZ);
    cmfsm_main<<<sms, 256, SMEMSZ>>>(lr, hr, w4, w5, s2w0, s2w1, s2w2, fw, (float*)d_out);
}

// round 11
// speedup vs baseline: 2.0264x; 1.2746x over previous
#include <cuda_runtime.h>
#include <cstdint>

typedef unsigned u32;

#define NPX (512 * 1024)
#define LRN (256 * 512)
#define NTILES 4096            // 4096 tiles x 128 px
#define BSTR 136               // act buffer row stride (floats)

// ---------------- packed-bf16 split weights in global scratch ----------------
// wh[m][kp] = pack(bf16(w[m][2kp]), bf16(w[m][2kp+1])); wl = residual pairs.
__device__ __align__(16) u32 g_wh0[128 * 68];
__device__ __align__(16) u32 g_wl0[128 * 68];
__device__ __align__(16) u32 g_wh1[64 * 68];
__device__ __align__(16) u32 g_wl1[64 * 68];
__device__ __align__(16) u32 g_wh2[32 * 36];
__device__ __align__(16) u32 g_wl2[32 * 36];
__device__ __align__(16) u32 g_wh3[16 * 20];
__device__ __align__(16) u32 g_wl3[16 * 20];

// pack two fp32 -> bf16x2 (lo half = first arg, hi half = second arg)
__device__ __forceinline__ u32 pkbf(float lo, float hi) {
    u32 r; asm("cvt.rn.bf16x2.f32 %0, %1, %2;" : "=r"(r) : "f"(hi), "f"(lo)); return r;
}
__device__ __forceinline__ float bflo(u32 p) { return __uint_as_float(p << 16); }
__device__ __forceinline__ float bfhi(u32 p) { return __uint_as_float(p & 0xFFFF0000u); }
__device__ __forceinline__ float lrelu(float x) { return fmaxf(x, 0.01f * x); }

// ---------------- prep: fp32 weights -> packed bf16 hi/lo layouts ----------------
__global__ void cmfsm_prep(const float* __restrict__ w0, const float* __restrict__ w1,
                           const float* __restrict__ w2, const float* __restrict__ w3) {
    int t = blockIdx.x * blockDim.x + threadIdx.x;
    int n = gridDim.x * blockDim.x;
    for (int i = t; i < 128 * 64; i += n) {           // W0 [128][128] -> 64 pairs, stride 68
        int m = i >> 6, kp = i & 63;
        float v0 = w0[m * 128 + 2 * kp], v1 = w0[m * 128 + 2 * kp + 1];
        u32 h = pkbf(v0, v1);
        g_wh0[m * 68 + kp] = h;
        g_wl0[m * 68 + kp] = pkbf(v0 - bflo(h), v1 - bfhi(h));
    }
    for (int i = t; i < 64 * 64; i += n) {            // W1 [64][128]
        int m = i >> 6, kp = i & 63;
        float v0 = w1[m * 128 + 2 * kp], v1 = w1[m * 128 + 2 * kp + 1];
        u32 h = pkbf(v0, v1);
        g_wh1[m * 68 + kp] = h;
        g_wl1[m * 68 + kp] = pkbf(v0 - bflo(h), v1 - bfhi(h));
    }
    for (int i = t; i < 32 * 32; i += n) {            // W2 [32][64] -> 32 pairs, stride 36
        int m = i >> 5, kp = i & 31;
        float v0 = w2[m * 64 + 2 * kp], v1 = w2[m * 64 + 2 * kp + 1];
        u32 h = pkbf(v0, v1);
        g_wh2[m * 36 + kp] = h;
        g_wl2[m * 36 + kp] = pkbf(v0 - bflo(h), v1 - bfhi(h));
    }
    for (int i = t; i < 16 * 16; i += n) {            // W3 [16][32] -> 16 pairs, stride 20
        int m = i >> 4, kp = i & 15;
        float v0 = w3[m * 32 + 2 * kp], v1 = w3[m * 32 + 2 * kp + 1];
        u32 h = pkbf(v0, v1);
        g_wh3[m * 20 + kp] = h;
        g_wl3[m * 20 + kp] = pkbf(v0 - bflo(h), v1 - bfhi(h));
    }
}

// ---------------- smem layout (bytes) ----------------
#define OBUF  0                         // act buffer: 128 rows x 136 f32 = 69632
#define OWH0  69632                     // 128x68 u32 = 34816
#define OWL0  104448
#define OWH1  139264                    // 64x68 = 17408
#define OWL1  156672
#define OWH2  174080                    // 32x36 = 4608
#define OWL2  178688
#define OWH3  183296                    // 16x20 = 1280
#define OWL3  184576
#define OSACT 185856                    // 128 px x 17 f32 = 8704
#define SMEMSZ 194560

// ---------------- mma.m16n8k16 bf16 ----------------
__device__ __forceinline__ void mma16(float* c, const u32* a, u32 b0, u32 b1) {
    asm volatile(
        "mma.sync.aligned.m16n8k16.row.col.f32.bf16.bf16.f32 "
        "{%0,%1,%2,%3}, {%4,%5,%6,%7}, {%8,%9}, {%0,%1,%2,%3};"
        : "+f"(c[0]), "+f"(c[1]), "+f"(c[2]), "+f"(c[3])
        : "r"(a[0]), "r"(a[1]), "r"(a[2]), "r"(a[3]), "r"(b0), "r"(b1));
}

// A-fragment in packed-pair space: rows (r, r+8), pair-cols (c, c+4)
__device__ __forceinline__ void lda(const u32* W, int S, int m0, int kp0, int lane, u32* a) {
    int r = lane >> 2, c = lane & 3;
    const u32* p = W + (m0 + r) * S + kp0 + c;
    a[0] = p[0];
    a[2] = p[4];
    a[1] = p[8 * S];
    a[3] = p[8 * S + 4];
}

// GEMM: C[MT][NT][4] += (Wh+Wl) @ (bh+bl), 3-term bf16. K = 16*KT.
template <int MT, int NT, int KT, int WS>
__device__ __forceinline__ void gemm(const u32* Wh, const u32* Wl, const float* buf,
                                     float* C, int m0, int px0, int lane) {
    const int r = lane >> 2, c = lane & 3;
#pragma unroll 2
    for (int kt = 0; kt < KT; kt++) {
        const int k0 = kt * 16;      // element-k base
        const int kp0 = kt * 8;      // pair base
        u32 ah[MT][4], al[MT][4];
#pragma unroll
        for (int mt = 0; mt < MT; mt++) {
            lda(Wh, WS, m0 + 16 * mt, kp0, lane, ah[mt]);
            lda(Wl, WS, m0 + 16 * mt, kp0, lane, al[mt]);
        }
#pragma unroll
        for (int nt = 0; nt < NT; nt++) {
            const int pxn = px0 + 8 * nt + r;
            float y0 = buf[(k0 + 2 * c) * BSTR + pxn];
            float y1 = buf[(k0 + 2 * c + 1) * BSTR + pxn];
            float y2 = buf[(k0 + 2 * c + 8) * BSTR + pxn];
            float y3 = buf[(k0 + 2 * c + 9) * BSTR + pxn];
            u32 bh0 = pkbf(y0, y1), bh1 = pkbf(y2, y3);
            u32 bl0 = pkbf(y0 - bflo(bh0), y1 - bfhi(bh0));
            u32 bl1 = pkbf(y2 - bflo(bh1), y3 - bfhi(bh1));
#pragma unroll
            for (int mt = 0; mt < MT; mt++) {
                float* cc = C + (mt * NT + nt) * 4;
                mma16(cc, ah[mt], bh0, bh1);
                mma16(cc, ah[mt], bl0, bl1);
                mma16(cc, al[mt], bh0, bh1);
            }
        }
    }
}

// epilogue: lrelu(C) -> buf (fp32), in place over inputs (caller syncs first)
template <int MT, int NT>
__device__ __forceinline__ void epi(float* buf, const float* C, int m0, int px0, int lane) {
    const int r = lane >> 2, c = lane & 3;
#pragma unroll
    for (int mt = 0; mt < MT; mt++)
#pragma unroll
        for (int nt = 0; nt < NT; nt++) {
            const float* cc = C + (mt * NT + nt) * 4;
            int ch = m0 + 16 * mt + r;
            int px = px0 + 8 * nt + 2 * c;
            float2 v0 = { lrelu(cc[0]), lrelu(cc[1]) };
            float2 v1 = { lrelu(cc[2]), lrelu(cc[3]) };
            *(float2*)(buf + ch * BSTR + px)       = v0;
            *(float2*)(buf + (ch + 8) * BSTR + px) = v1;
        }
}

__global__ void __launch_bounds__(256, 1)
cmfsm_main(const float* __restrict__ lr, const float* __restrict__ hr,
           const float* __restrict__ w4, const float* __restrict__ w5,
           const float* __restrict__ s2w0, const float* __restrict__ s2w1,
           const float* __restrict__ s2w2, const float* __restrict__ fw,
           float* __restrict__ out) {
    extern __shared__ __align__(16) char sm8[];
    float* buf = (float*)(sm8 + OBUF);
    u32* wh0 = (u32*)(sm8 + OWH0);  u32* wl0 = (u32*)(sm8 + OWL0);
    u32* wh1 = (u32*)(sm8 + OWH1);  u32* wl1 = (u32*)(sm8 + OWL1);
    u32* wh2 = (u32*)(sm8 + OWH2);  u32* wl2 = (u32*)(sm8 + OWL2);
    u32* wh3 = (u32*)(sm8 + OWH3);  u32* wl3 = (u32*)(sm8 + OWL3);
    float* sact = (float*)(sm8 + OSACT);

    const int tid  = threadIdx.x;
    const int wid  = tid >> 5;
    const int lane = tid & 31;

    // weights: L2 scratch -> smem, once per (persistent) block
    {
        const uint4* s; uint4* d;
        s = (const uint4*)g_wh0; d = (uint4*)wh0;
        for (int i = tid; i < 2176; i += 256) d[i] = s[i];
        s = (const uint4*)g_wl0; d = (uint4*)wl0;
        for (int i = tid; i < 2176; i += 256) d[i] = s[i];
        s = (const uint4*)g_wh1; d = (uint4*)wh1;
        for (int i = tid; i < 1088; i += 256) d[i] = s[i];
        s = (const uint4*)g_wl1; d = (uint4*)wl1;
        for (int i = tid; i < 1088; i += 256) d[i] = s[i];
        s = (const uint4*)g_wh2; d = (uint4*)wh2;
        for (int i = tid; i < 288; i += 256) d[i] = s[i];
        s = (const uint4*)g_wl2; d = (uint4*)wl2;
        for (int i = tid; i < 288; i += 256) d[i] = s[i];
        s = (const uint4*)g_wh3; d = (uint4*)wh3;
        for (int i = tid; i < 80; i += 256) d[i] = s[i];
        s = (const uint4*)g_wl3; d = (uint4*)wl3;
        for (int i = tid; i < 80; i += 256) d[i] = s[i];
    }
    __syncthreads();

    for (int tile = blockIdx.x; tile < NTILES; tile += gridDim.x) {
        const int pxb = tile << 7;
        const int hb  = pxb >> 10;
        const int wbp = pxb & 1023;

        // ---- rep build: rows 0-31 a, 32-63 b, 64-95 a*b, 96-127 (a-b)^2 ----
        {
            const int g  = tid >> 7;          // 0..1 -> 16 channels each
            const int px = tid & 127;
            const int li = ((hb >> 1) << 9) + ((wbp + px) >> 1);
            const float* hp = hr + (size_t)(16 * g) * NPX + (pxb + px);
            const float* lp = lr + (size_t)(16 * g) * LRN + li;
#pragma unroll
            for (int i = 0; i < 16; i++) {
                float a = lp[(size_t)i * LRN];
                float b = hp[(size_t)i * NPX];
                int cch = 16 * g + i;
                buf[cch * BSTR + px]        = a;
                buf[(32 + cch) * BSTR + px] = b;
                buf[(64 + cch) * BSTR + px] = a * b;
                float d = a - b;
                buf[(96 + cch) * BSTR + px] = d * d;
            }
        }
        __syncthreads();

        // ---- GEMM1: 128 <- rep(128); warp grid 4(m) x 2(px) ----
        {
            float C1[2 * 8 * 4];
#pragma unroll
            for (int i = 0; i < 64; i++) C1[i] = 0.f;
            int m0 = 32 * (wid & 3), px0 = 64 * (wid >> 2);
            gemm<2, 8, 8, 68>(wh0, wl0, buf, C1, m0, px0, lane);
            __syncthreads();
            epi<2, 8>(buf, C1, m0, px0, lane);
        }
        __syncthreads();

        // ---- GEMM2: 64 <- act1(128); warp grid 2(m) x 4(px) ----
        {
            float C2[2 * 4 * 4];
#pragma unroll
            for (int i = 0; i < 32; i++) C2[i] = 0.f;
            int m0 = 32 * (wid & 1), px0 = 32 * (wid >> 1);
            gemm<2, 4, 8, 68>(wh1, wl1, buf, C2, m0, px0, lane);
            __syncthreads();
            epi<2, 4>(buf, C2, m0, px0, lane);
        }
        __syncthreads();

        // ---- GEMM3: 32 <- act2(64); warp grid 2(m) x 4(px) ----
        {
            float C3[1 * 4 * 4];
#pragma unroll
            for (int i = 0; i < 16; i++) C3[i] = 0.f;
            int m0 = 16 * (wid & 1), px0 = 32 * (wid >> 1);
            gemm<1, 4, 4, 36>(wh2, wl2, buf, C3, m0, px0, lane);
            __syncthreads();
            epi<1, 4>(buf, C3, m0, px0, lane);
        }
        __syncthreads();

        // ---- GEMM4: 16 <- act3(32); 8 warps x 16 px (NT=2) -> SACT [px][16] ----
        {
            float C4[2 * 4];
#pragma unroll
            for (int i = 0; i < 8; i++) C4[i] = 0.f;
            int px0 = 16 * wid;
            gemm<1, 2, 2, 20>(wh3, wl3, buf, C4, 0, px0, lane);
            const int r = lane >> 2, c = lane & 3;
#pragma unroll
            for (int nt = 0; nt < 2; nt++) {
                const float* cc = C4 + nt * 4;
                int px = px0 + 8 * nt + 2 * c;
                sact[px * 17 + r]           = lrelu(cc[0]);
                sact[(px + 1) * 17 + r]     = lrelu(cc[1]);
                sact[px * 17 + r + 8]       = lrelu(cc[2]);
                sact[(px + 1) * 17 + r + 8] = lrelu(cc[3]);
            }
        }
        __syncthreads();

        // ---- scalar finish: layers 5,6 + weights2 + fuse (exact fp32) ----
        if (tid < 128) {
            const float* o4 = sact + tid * 17;
            float w1v = 0.f;
#pragma unroll
            for (int cc = 0; cc < 8; cc++) {
                float n5 = 0.f;
#pragma unroll
                for (int k = 0; k < 16; k++) n5 = fmaf(w4[cc * 16 + k], o4[k], n5);
                w1v = fmaf(w5[cc], n5, w1v);
            }
            float dx = ((wbp + tid) & 1) ? 1.0f : -1.0f;
            float dy = (hb & 1) ? 1.0f : -1.0f;
            const float nm = 1.41421356237309515f;
            float t0 = lrelu(s2w0[0] * dx + s2w0[1] * dy + s2w0[2] * nm);
            float t1 = lrelu(s2w0[3] * dx + s2w0[4] * dy + s2w0[5] * nm);
            float t2 = lrelu(s2w0[6] * dx + s2w0[7] * dy + s2w0[8] * nm);
            float u0 = lrelu(s2w1[0] * t0 + s2w1[1] * t1 + s2w1[2] * t2);
            float u1 = lrelu(s2w1[3] * t0 + s2w1[4] * t1 + s2w1[5] * t2);
            float w2v = s2w2[0] * u0 + s2w2[1] * u1;
            out[pxb + tid] = fabsf(fw[0]) * w1v + fabsf(fw[1]) * w2v;
        }
        __syncthreads();
    }
}

extern "C" void kernel_launch(void* const* d_in, const int* in_sizes, int n_in,
                              void* d_out, int out_size) {
    const float* lr   = (const float*)d_in[0];
    const float* hr   = (const float*)d_in[1];
    const float* w0   = (const float*)d_in[2];
    const float* w1   = (const float*)d_in[3];
    const float* w2   = (const float*)d_in[4];
    const float* w3   = (const float*)d_in[5];
    const float* w4   = (const float*)d_in[6];
    const float* w5   = (const float*)d_in[7];
    const float* s2w0 = (const float*)d_in[8];
    const float* s2w1 = (const float*)d_in[9];
    const float* s2w2 = (const float*)d_in[10];
    const float* fw   = (const float*)d_in[11];

    cmfsm_prep<<<64, 256>>>(w0, w1, w2, w3);

    int sms = 148;
    cudaDeviceGetAttribute(&sms, cudaDevAttrMultiProcessorCount, 0);
    if (sms > NTILES) sms = NTILES;

    cudaFuncSetAttribute(cmfsm_main, cudaFuncAttributeMaxDynamicSharedMemorySize, SMEMSZ);
    cmfsm_main<<<sms, 256, SMEMSZ>>>(lr, hr, w4, w5, s2w0, s2w1, s2w2, fw, (float*)d_out);
}